// round 14
// baseline (speedup 1.0000x reference)
#include <cuda_runtime.h>

#define IH 1024
#define IW 1024
#define IMG_PIX (IH * IW)
#define NSEG 32            // row segments per image (16 cell rows each)
#define SEG_ROWS 16
#define COLW 17            // col-warps per row strip (31 owned cell cols each)
#define WPB 4              // warps per block

typedef unsigned long long ull;

__device__ __forceinline__ float tanhf_fast(float x) {
    float y; asm("tanh.approx.f32 %0, %1;" : "=f"(y) : "f"(x)); return y;
}
__device__ __forceinline__ ull pack2(float lo, float hi) {
    ull r; asm("mov.b64 %0, {%1, %2};" : "=l"(r) : "f"(lo), "f"(hi)); return r;
}
__device__ __forceinline__ void unpack2(ull v, float& lo, float& hi) {
    asm("mov.b64 {%0, %1}, %2;" : "=f"(lo), "=f"(hi) : "l"(v));
}
__device__ __forceinline__ ull fma2(ull a, ull b, ull c) {
    ull r; asm("fma.rn.f32x2 %0, %1, %2, %3;" : "=l"(r) : "l"(a), "l"(b), "l"(c)); return r;
}

__global__ __launch_bounds__(128, 8)
void ae_kernel(const float* __restrict__ img,
               const float* __restrict__ w_conv,  // (2,1,2,2)
               const float* __restrict__ b_conv,  // (2,)
               const float* __restrict__ W_b,     // (2,2)
               const float* __restrict__ b_b,     // (2,)
               const float* __restrict__ W_d,     // (2,1,2,2)
               const float* __restrict__ b_d,     // (1,)
               float* __restrict__ out)
{
    const int lane = threadIdx.x & 31;
    const int gw   = blockIdx.x * WPB + (threadIdx.x >> 5);
    const int c    = gw % COLW;          // col-warp
    const int t    = gw / COLW;
    const int s    = t & (NSEG - 1);     // row segment
    const int im   = t >> 5;             // image

    // ---- tiny weights -> registers (uniform) ----
    const float4 wc0 = __ldg((const float4*)w_conv);
    const float4 wc1 = __ldg((const float4*)(w_conv + 4));
    const float2 bc  = __ldg((const float2*)b_conv);
    const float4 wb  = __ldg((const float4*)W_b);
    const float2 bb  = __ldg((const float2*)b_b);
    ull wd0p01, wd0p23, wd1p01, wd1p23, bdp;
    {
        const float4 t0 = __ldg((const float4*)W_d);
        const float4 t1 = __ldg((const float4*)(W_d + 4));
        wd0p01 = pack2(t0.x * 0.5f, t0.y * 0.5f);
        wd0p23 = pack2(t0.z * 0.5f, t0.w * 0.5f);
        wd1p01 = pack2(t1.x * 0.5f, t1.y * 0.5f);
        wd1p23 = pack2(t1.z * 0.5f, t1.w * 0.5f);
    }
    const float bdh = __ldg(b_d) * 0.5f;
    bdp = pack2(bdh, bdh);
    const float thc = tanhf_fast(bdh);

    // ---- lane geometry (invariant) ----
    const int kc = 31 * c + lane - 1;     // own patch col (may be -1 or >510)
    const int CB = kc + 1;                // own cell col
    const float hfk = ((unsigned)kc <= 510u) ? 0.5f : 0.0f;
    const float hfc = fmaf(thc, hfk, hfk);     // constant-quadrant value (steady loop)
    const int colf = (int)((unsigned)kc <= 510u) + (int)((unsigned)CB <= 510u);
    const float rcp_mid  = (colf == 2) ? 0.25f : 0.5f;   // interior cell rows
    const float rcp_edge = (colf == 2) ? 0.5f  : 1.0f;   // cell rows 0 and 511
    const bool cell_ok = (lane < 31) && (CB <= 511);

    // clamped column bases (OOB patches have hf=0; clamped garbage never escapes)
    const int gcL = 2 * kc;
    const int colO = min(max(gcL, 0), 1022);       // own block cols
    const int colR = min(max(gcL + 2, 0), 1022);   // right block cols

    const float* ibase = img + (size_t)im * IMG_PIX;
    const float* pO = ibase + colO;
    const float* pR = ibase + colR;
    float* op = out + (size_t)im * IMG_PIX + (size_t)(32 * s) * IW + 2 * CB;

    // loop-side load: row needs only upper clamp (2b >= 0 in steady loop)
    auto LOADBR = [&](int b, float4& O, float4& R) {
        const int ro = min(2 * b, 1022);
        const long long off = (long long)ro * IW;
        const float2 ot  = *(const float2*)(pO + off);
        const float2 rt  = *(const float2*)(pR + off);
        const float2 obm = *(const float2*)(pO + off + IW);
        const float2 rb  = *(const float2*)(pR + off + IW);
        O = make_float4(ot.x, ot.y, obm.x, obm.y);
        R = make_float4(rt.x, rt.y, rb.x, rb.y);
    };
    // prologue load: full clamp (row may be negative)
    auto LOADBR_C = [&](int b, float4& O, float4& R) {
        const int ro = min(max(2 * b, 0), 1022);
        const long long off = (long long)ro * IW;
        const float2 ot  = *(const float2*)(pO + off);
        const float2 rt  = *(const float2*)(pR + off);
        const float2 obm = *(const float2*)(pO + off + IW);
        const float2 rb  = *(const float2*)(pR + off + IW);
        O = make_float4(ot.x, ot.y, obm.x, obm.y);
        R = make_float4(rt.x, rt.y, rb.x, rb.y);
    };

#define CONVB(e, B) do { \
        cv0[e] = fmaf(wc0.x, (B).x, fmaf(wc0.y, (B).y, fmaf(wc0.z, (B).z, fmaf(wc0.w, (B).w, bc.x)))); \
        cv1[e] = fmaf(wc1.x, (B).x, fmaf(wc1.y, (B).y, fmaf(wc1.z, (B).z, fmaf(wc1.w, (B).w, bc.y)))); \
        } while (0)

    // raw conv values in cv -> am/z/tanh sets; HF = patch-validity half-scale
#define PATCH_CORE(HF, HFC)                                                   \
        int am0 = 0, am1 = 0;                                                 \
        float mv0 = cv0[0], mv1 = cv1[0];                                     \
        _Pragma("unroll")                                                     \
        for (int e = 1; e < 4; e++) {                                         \
            if (cv0[e] > mv0) { mv0 = cv0[e]; am0 = e; }                      \
            if (cv1[e] > mv1) { mv1 = cv1[e]; am1 = e; }                      \
        }                                                                     \
        am0 = (mv0 > 0.0f) ? am0 : 0;  mv0 = fmaxf(mv0, 0.0f);                \
        am1 = (mv1 > 0.0f) ? am1 : 0;  mv1 = fmaxf(mv1, 0.0f);                \
        const float z0 = fmaxf(fmaf(mv0, wb.x, fmaf(mv1, wb.y, bb.x)), 0.0f); \
        const float z1 = fmaxf(fmaf(mv0, wb.z, fmaf(mv1, wb.w, bb.y)), 0.0f); \
        const float zz1 = (am0 == am1) ? z1 : 0.0f;                           \
        const ull z0p  = pack2(z0, z0);                                       \
        const ull zz1p = pack2(zz1, zz1);                                     \
        const ull z1p  = pack2(z1, z1);                                       \
        const ull a01 = fma2(z0p, wd0p01, fma2(zz1p, wd1p01, bdp));           \
        const ull a23 = fma2(z0p, wd0p23, fma2(zz1p, wd1p23, bdp));           \
        const ull b01 = fma2(z1p, wd1p01, bdp);                               \
        const ull b23 = fma2(z1p, wd1p23, bdp);                               \
        float ar[4], br[4];                                                   \
        unpack2(a01, ar[0], ar[1]);  unpack2(a23, ar[2], ar[3]);              \
        unpack2(b01, br[0], br[1]);  unpack2(b23, br[2], br[3]);              \
        float th0s[4], th1s[4];                                               \
        _Pragma("unroll")                                                     \
        for (int pq = 0; pq < 4; pq++) {                                      \
            th0s[pq] = fmaf(tanhf_fast(ar[pq]), (HF), (HF));                  \
            th1s[pq] = fmaf(tanhf_fast(br[pq]), (HF), (HF));                  \
        }

#define GRP(dst, g, HFC) do {                                                 \
        const bool p0 = (am0 == (g));                                         \
        const bool p1 = (am1 == (g));                                         \
        (dst).x = p0 ? th0s[0] : (p1 ? th1s[0] : (HFC));                      \
        (dst).y = p0 ? th0s[1] : (p1 ? th1s[1] : (HFC));                      \
        (dst).z = p0 ? th0s[2] : (p1 ? th1s[2] : (HFC));                      \
        (dst).w = p0 ? th0s[3] : (p1 ? th1s[3] : (HFC)); } while (0)

    // ---- window init: Ow[1]=block row pr0, Ow[0]=block row pr0+1 ----
    float4 Ow[2], Rw[2];
    const int pr0 = 16 * s - 1;           // warm-up patch row
    LOADBR_C(pr0,     Ow[1], Rw[1]);
    LOADBR_C(pr0 + 1, Ow[0], Rw[0]);

    float4 carry;
    {   // ---- peeled warm-up (patch row pr0): only BL/BR groups needed ----
        const float hf0  = (s == 0) ? 0.0f : hfk;     // pr0 invalid only for s==0
        const float hfc0 = fmaf(thc, hf0, hf0);
        float cv0[4], cv1[4];
        CONVB(0, Ow[1]); CONVB(1, Rw[1]); CONVB(2, Ow[0]); CONVB(3, Rw[0]);
        LOADBR(pr0 + 2, Ow[1], Rw[1]);    // refill slot 1 with row pr0+2 (row >= 0+)
        PATCH_CORE(hf0, hfc0)
        float4 gBL, gBR;
        GRP(gBL, 2, hfc0);
        GRP(gBR, 3, hfc0);
        carry.x = gBR.x + __shfl_down_sync(0xffffffffu, gBL.x, 1);
        carry.y = gBR.y + __shfl_down_sync(0xffffffffu, gBL.y, 1);
        carry.z = gBR.z + __shfl_down_sync(0xffffffffu, gBL.z, 1);
        carry.w = gBR.w + __shfl_down_sync(0xffffffffu, gBL.w, 1);
    }

    // steady loop: all computed patches are fully valid (hf = hfk)
    const int nit = (s == NSEG - 1) ? (SEG_ROWS - 1) : SEG_ROWS;
#pragma unroll 2
    for (int i = 1; i <= nit; i++) {
        const int pr = pr0 + i;           // patch row (== emitted cell row)
        const int lo = (i + 1) & 1;       // slot of block row pr
        const int hi = i & 1;             // slot of block row pr+1

        float cv0[4], cv1[4];
        CONVB(0, Ow[lo]); CONVB(1, Rw[lo]); CONVB(2, Ow[hi]); CONVB(3, Rw[hi]);
        LOADBR(pr + 2, Ow[lo], Rw[lo]);   // refill consumed slot

        PATCH_CORE(hfk, hfc)

        float4 gTL, gTR, gBL, gBR;
        GRP(gTL, 0, hfc); GRP(gTR, 1, hfc); GRP(gBL, 2, hfc); GRP(gBR, 3, hfc);

        // horizontal routing from lane+1
        float4 nTL, nBL;
        nTL.x = __shfl_down_sync(0xffffffffu, gTL.x, 1);
        nTL.y = __shfl_down_sync(0xffffffffu, gTL.y, 1);
        nTL.z = __shfl_down_sync(0xffffffffu, gTL.z, 1);
        nTL.w = __shfl_down_sync(0xffffffffu, gTL.w, 1);
        nBL.x = __shfl_down_sync(0xffffffffu, gBL.x, 1);
        nBL.y = __shfl_down_sync(0xffffffffu, gBL.y, 1);
        nBL.z = __shfl_down_sync(0xffffffffu, gBL.z, 1);
        nBL.w = __shfl_down_sync(0xffffffffu, gBL.w, 1);

        // emit cell row pr
        if (cell_ok) {
            const float rcp = (pr == 0) ? rcp_edge : rcp_mid;
            const float pix00 = (carry.x + gTR.x) + nTL.x;
            const float pix01 = (carry.y + gTR.y) + nTL.y;
            const float pix10 = (carry.z + gTR.z) + nTL.z;
            const float pix11 = (carry.w + gTR.w) + nTL.w;
            *(float2*)(op)      = make_float2(pix00 * rcp, pix01 * rcp);
            *(float2*)(op + IW) = make_float2(pix10 * rcp, pix11 * rcp);
        }
        op += 2 * IW;

        // vertical carry for next cell row
        carry.x = gBR.x + nBL.x;
        carry.y = gBR.y + nBL.y;
        carry.z = gBR.z + nBL.z;
        carry.w = gBR.w + nBL.w;
    }

    // ---- epilogue for the last segment: cell row 511 has no bottom patches ----
    if (s == NSEG - 1 && cell_ok) {
        *(float2*)(op)      = make_float2(carry.x * rcp_edge, carry.y * rcp_edge);
        *(float2*)(op + IW) = make_float2(carry.z * rcp_edge, carry.w * rcp_edge);
    }
#undef GRP
#undef PATCH_CORE
#undef CONVB
}

extern "C" void kernel_launch(void* const* d_in, const int* in_sizes, int n_in,
                              void* d_out, int out_size) {
    const float* img    = (const float*)d_in[0];
    const float* w_conv = (const float*)d_in[1];
    const float* b_conv = (const float*)d_in[2];
    const float* W_b    = (const float*)d_in[3];
    const float* b_b    = (const float*)d_in[4];
    const float* W_d    = (const float*)d_in[5];
    const float* b_d    = (const float*)d_in[6];
    float* out = (float*)d_out;

    // 8 imgs x 32 segments x 17 col-warps = 4352 warps / 4 per block
    dim3 grid(8 * NSEG * COLW / WPB);   // 1088 blocks
    dim3 block(128);
    ae_kernel<<<grid, block>>>(img, w_conv, b_conv, W_b, b_b, W_d, b_d, out);
}

// round 15
// speedup vs baseline: 1.0014x; 1.0014x over previous
#include <cuda_runtime.h>

#define IH 1024
#define IW 1024
#define IMG_PIX (IH * IW)
#define NSEG 32            // row segments per image (16 cell rows each)
#define SEG_ROWS 16
#define COLW 17            // col-warps per row strip (31 owned cell cols each)
#define WPB 4              // warps per block

__device__ __forceinline__ float tanhf_fast(float x) {
    float y; asm("tanh.approx.f32 %0, %1;" : "=f"(y) : "f"(x)); return y;
}

__global__ __launch_bounds__(128, 8)
void ae_kernel(const float* __restrict__ img,
               const float* __restrict__ w_conv,  // (2,1,2,2)
               const float* __restrict__ b_conv,  // (2,)
               const float* __restrict__ W_b,     // (2,2)
               const float* __restrict__ b_b,     // (2,)
               const float* __restrict__ W_d,     // (2,1,2,2)
               const float* __restrict__ b_d,     // (1,)
               float* __restrict__ out)
{
    const int lane = threadIdx.x & 31;
    const int gw   = blockIdx.x * WPB + (threadIdx.x >> 5);
    const int c    = gw % COLW;          // col-warp
    const int t    = gw / COLW;
    const int s    = t & (NSEG - 1);     // row segment
    const int im   = t >> 5;             // image

    // ---- tiny weights -> registers (uniform) ----
    const float4 wc0 = __ldg((const float4*)w_conv);
    const float4 wc1 = __ldg((const float4*)(w_conv + 4));
    const float2 bc  = __ldg((const float2*)b_conv);
    const float4 wb  = __ldg((const float4*)W_b);
    const float2 bb  = __ldg((const float2*)b_b);
    float wd0h[4], wd1h[4];
    {
        const float4 t0 = __ldg((const float4*)W_d);
        const float4 t1 = __ldg((const float4*)(W_d + 4));
        wd0h[0]=t0.x*0.5f; wd0h[1]=t0.y*0.5f; wd0h[2]=t0.z*0.5f; wd0h[3]=t0.w*0.5f;
        wd1h[0]=t1.x*0.5f; wd1h[1]=t1.y*0.5f; wd1h[2]=t1.z*0.5f; wd1h[3]=t1.w*0.5f;
    }
    const float bdh = __ldg(b_d) * 0.5f;
    const float thc = tanhf_fast(bdh);

    // ---- lane geometry (invariant) ----
    const int kc = 31 * c + lane - 1;     // own patch col (may be -1 or >510)
    const int CB = kc + 1;                // own cell col
    const float hfk = ((unsigned)kc <= 510u) ? 0.5f : 0.0f;
    const float hfc = fmaf(thc, hfk, hfk);     // constant-quadrant value (steady loop)
    const int colf = (int)((unsigned)kc <= 510u) + (int)((unsigned)CB <= 510u);
    const float rcp_mid  = (colf == 2) ? 0.25f : 0.5f;   // interior cell rows
    const float rcp_edge = (colf == 2) ? 0.5f  : 1.0f;   // cell rows 0 and 511
    const bool cell_ok = (lane < 31) && (CB <= 511);

    // clamped column bases (OOB patches have hf=0; clamped garbage never escapes)
    const int gcL = 2 * kc;
    const int colO = min(max(gcL, 0), 1022);       // own block cols
    const int colR = min(max(gcL + 2, 0), 1022);   // right block cols

    const float* ibase = img + (size_t)im * IMG_PIX;
    const float* pO = ibase + colO;
    const float* pR = ibase + colR;
    float* op = out + (size_t)im * IMG_PIX + (size_t)(32 * s) * IW + 2 * CB;

    // loop-side load: row needs only upper clamp (2b >= 0 in steady loop)
    auto LOADBR = [&](int b, float4& O, float4& R) {
        const int ro = min(2 * b, 1022);
        const long long off = (long long)ro * IW;
        const float2 ot  = *(const float2*)(pO + off);
        const float2 rt  = *(const float2*)(pR + off);
        const float2 obm = *(const float2*)(pO + off + IW);
        const float2 rb  = *(const float2*)(pR + off + IW);
        O = make_float4(ot.x, ot.y, obm.x, obm.y);
        R = make_float4(rt.x, rt.y, rb.x, rb.y);
    };
    // prologue load: full clamp (row may be negative)
    auto LOADBR_C = [&](int b, float4& O, float4& R) {
        const int ro = min(max(2 * b, 0), 1022);
        const long long off = (long long)ro * IW;
        const float2 ot  = *(const float2*)(pO + off);
        const float2 rt  = *(const float2*)(pR + off);
        const float2 obm = *(const float2*)(pO + off + IW);
        const float2 rb  = *(const float2*)(pR + off + IW);
        O = make_float4(ot.x, ot.y, obm.x, obm.y);
        R = make_float4(rt.x, rt.y, rb.x, rb.y);
    };

#define CONVB(e, B) do { \
        cv0[e] = fmaf(wc0.x, (B).x, fmaf(wc0.y, (B).y, fmaf(wc0.z, (B).z, fmaf(wc0.w, (B).w, bc.x)))); \
        cv1[e] = fmaf(wc1.x, (B).x, fmaf(wc1.y, (B).y, fmaf(wc1.z, (B).z, fmaf(wc1.w, (B).w, bc.y)))); \
        } while (0)

    // raw conv values in cv -> argmax (deferred ReLU) -> z -> 8 scalar tanh args
#define PATCH_CORE(HF)                                                        \
        int am0 = 0, am1 = 0;                                                 \
        float mv0 = cv0[0], mv1 = cv1[0];                                     \
        _Pragma("unroll")                                                     \
        for (int e = 1; e < 4; e++) {                                         \
            if (cv0[e] > mv0) { mv0 = cv0[e]; am0 = e; }                      \
            if (cv1[e] > mv1) { mv1 = cv1[e]; am1 = e; }                      \
        }                                                                     \
        am0 = (mv0 > 0.0f) ? am0 : 0;  mv0 = fmaxf(mv0, 0.0f);                \
        am1 = (mv1 > 0.0f) ? am1 : 0;  mv1 = fmaxf(mv1, 0.0f);                \
        const float z0 = fmaxf(fmaf(mv0, wb.x, fmaf(mv1, wb.y, bb.x)), 0.0f); \
        const float z1 = fmaxf(fmaf(mv0, wb.z, fmaf(mv1, wb.w, bb.y)), 0.0f); \
        const float zz1 = (am0 == am1) ? z1 : 0.0f;                           \
        float th0s[4], th1s[4];                                               \
        _Pragma("unroll")                                                     \
        for (int pq = 0; pq < 4; pq++) {                                      \
            th0s[pq] = fmaf(tanhf_fast(fmaf(z0, wd0h[pq], fmaf(zz1, wd1h[pq], bdh))), (HF), (HF)); \
            th1s[pq] = fmaf(tanhf_fast(fmaf(z1, wd1h[pq], bdh)), (HF), (HF)); \
        }

#define GRP(dst, g, HFC) do {                                                 \
        const bool p0 = (am0 == (g));                                         \
        const bool p1 = (am1 == (g));                                         \
        (dst).x = p0 ? th0s[0] : (p1 ? th1s[0] : (HFC));                      \
        (dst).y = p0 ? th0s[1] : (p1 ? th1s[1] : (HFC));                      \
        (dst).z = p0 ? th0s[2] : (p1 ? th1s[2] : (HFC));                      \
        (dst).w = p0 ? th0s[3] : (p1 ? th1s[3] : (HFC)); } while (0)

    // ---- window init: Ow[1]=block row pr0, Ow[0]=block row pr0+1 ----
    float4 Ow[2], Rw[2];
    const int pr0 = 16 * s - 1;           // warm-up patch row
    LOADBR_C(pr0,     Ow[1], Rw[1]);
    LOADBR_C(pr0 + 1, Ow[0], Rw[0]);

    float4 carry;
    {   // ---- peeled warm-up (patch row pr0): only BL/BR groups needed ----
        const float hf0  = (s == 0) ? 0.0f : hfk;     // pr0 invalid only for s==0
        const float hfc0 = fmaf(thc, hf0, hf0);
        float cv0[4], cv1[4];
        CONVB(0, Ow[1]); CONVB(1, Rw[1]); CONVB(2, Ow[0]); CONVB(3, Rw[0]);
        LOADBR(pr0 + 2, Ow[1], Rw[1]);    // refill slot 1 with row pr0+2
        PATCH_CORE(hf0)
        float4 gBL, gBR;
        GRP(gBL, 2, hfc0);
        GRP(gBR, 3, hfc0);
        carry.x = gBR.x + __shfl_down_sync(0xffffffffu, gBL.x, 1);
        carry.y = gBR.y + __shfl_down_sync(0xffffffffu, gBL.y, 1);
        carry.z = gBR.z + __shfl_down_sync(0xffffffffu, gBL.z, 1);
        carry.w = gBR.w + __shfl_down_sync(0xffffffffu, gBL.w, 1);
    }

    // steady loop: all computed patches are fully valid (hf = hfk)
    const int nit = (s == NSEG - 1) ? (SEG_ROWS - 1) : SEG_ROWS;
#pragma unroll 2
    for (int i = 1; i <= nit; i++) {
        const int pr = pr0 + i;           // patch row (== emitted cell row)
        const int lo = (i + 1) & 1;       // slot of block row pr
        const int hi = i & 1;             // slot of block row pr+1

        float cv0[4], cv1[4];
        CONVB(0, Ow[lo]); CONVB(1, Rw[lo]); CONVB(2, Ow[hi]); CONVB(3, Rw[hi]);
        LOADBR(pr + 2, Ow[lo], Rw[lo]);   // refill consumed slot

        PATCH_CORE(hfk)

        float4 gTL, gTR, gBL, gBR;
        GRP(gTL, 0, hfc); GRP(gTR, 1, hfc); GRP(gBL, 2, hfc); GRP(gBR, 3, hfc);

        // horizontal routing from lane+1
        float4 nTL, nBL;
        nTL.x = __shfl_down_sync(0xffffffffu, gTL.x, 1);
        nTL.y = __shfl_down_sync(0xffffffffu, gTL.y, 1);
        nTL.z = __shfl_down_sync(0xffffffffu, gTL.z, 1);
        nTL.w = __shfl_down_sync(0xffffffffu, gTL.w, 1);
        nBL.x = __shfl_down_sync(0xffffffffu, gBL.x, 1);
        nBL.y = __shfl_down_sync(0xffffffffu, gBL.y, 1);
        nBL.z = __shfl_down_sync(0xffffffffu, gBL.z, 1);
        nBL.w = __shfl_down_sync(0xffffffffu, gBL.w, 1);

        // emit cell row pr
        if (cell_ok) {
            const float rcp = (pr == 0) ? rcp_edge : rcp_mid;
            const float pix00 = (carry.x + gTR.x) + nTL.x;
            const float pix01 = (carry.y + gTR.y) + nTL.y;
            const float pix10 = (carry.z + gTR.z) + nTL.z;
            const float pix11 = (carry.w + gTR.w) + nTL.w;
            *(float2*)(op)      = make_float2(pix00 * rcp, pix01 * rcp);
            *(float2*)(op + IW) = make_float2(pix10 * rcp, pix11 * rcp);
        }
        op += 2 * IW;

        // vertical carry for next cell row
        carry.x = gBR.x + nBL.x;
        carry.y = gBR.y + nBL.y;
        carry.z = gBR.z + nBL.z;
        carry.w = gBR.w + nBL.w;
    }

    // ---- epilogue for the last segment: cell row 511 has no bottom patches ----
    if (s == NSEG - 1 && cell_ok) {
        *(float2*)(op)      = make_float2(carry.x * rcp_edge, carry.y * rcp_edge);
        *(float2*)(op + IW) = make_float2(carry.z * rcp_edge, carry.w * rcp_edge);
    }
#undef GRP
#undef PATCH_CORE
#undef CONVB
}

extern "C" void kernel_launch(void* const* d_in, const int* in_sizes, int n_in,
                              void* d_out, int out_size) {
    const float* img    = (const float*)d_in[0];
    const float* w_conv = (const float*)d_in[1];
    const float* b_conv = (const float*)d_in[2];
    const float* W_b    = (const float*)d_in[3];
    const float* b_b    = (const float*)d_in[4];
    const float* W_d    = (const float*)d_in[5];
    const float* b_d    = (const float*)d_in[6];
    float* out = (float*)d_out;

    // 8 imgs x 32 segments x 17 col-warps = 4352 warps / 4 per block
    dim3 grid(8 * NSEG * COLW / WPB);   // 1088 blocks
    dim3 block(128);
    ae_kernel<<<grid, block>>>(img, w_conv, b_conv, W_b, b_b, W_d, b_d, out);
}

// round 16
// speedup vs baseline: 1.0992x; 1.0977x over previous
#include <cuda_runtime.h>

#define IH 1024
#define IW 1024
#define IMG_PIX (IH * IW)
#define NSEG 32            // row segments per image (16 cell rows each)
#define SEG_ROWS 16
#define COLW 17            // col-warps per row strip (31 owned cell cols each)
#define WPB 4              // warps per block

__device__ __forceinline__ float tanhf_fast(float x) {
    float y; asm("tanh.approx.f32 %0, %1;" : "=f"(y) : "f"(x)); return y;
}

__global__ __launch_bounds__(128, 8)
void ae_kernel(const float* __restrict__ img,
               const float* __restrict__ w_conv,  // (2,1,2,2)
               const float* __restrict__ b_conv,  // (2,)
               const float* __restrict__ W_b,     // (2,2)
               const float* __restrict__ b_b,     // (2,)
               const float* __restrict__ W_d,     // (2,1,2,2)
               const float* __restrict__ b_d,     // (1,)
               float* __restrict__ out)
{
    const int lane = threadIdx.x & 31;
    const int gw   = blockIdx.x * WPB + (threadIdx.x >> 5);
    const int c    = gw % COLW;          // col-warp
    const int t    = gw / COLW;
    const int s    = t & (NSEG - 1);     // row segment
    const int im   = t >> 5;             // image

    // ---- tiny weights -> registers (uniform) ----
    const float4 wc0 = __ldg((const float4*)w_conv);
    const float4 wc1 = __ldg((const float4*)(w_conv + 4));
    const float2 bc  = __ldg((const float2*)b_conv);
    const float4 wb  = __ldg((const float4*)W_b);
    const float2 bb  = __ldg((const float2*)b_b);
    float wd0h[4], wd1h[4];
    {
        const float4 t0 = __ldg((const float4*)W_d);
        const float4 t1 = __ldg((const float4*)(W_d + 4));
        wd0h[0]=t0.x*0.5f; wd0h[1]=t0.y*0.5f; wd0h[2]=t0.z*0.5f; wd0h[3]=t0.w*0.5f;
        wd1h[0]=t1.x*0.5f; wd1h[1]=t1.y*0.5f; wd1h[2]=t1.z*0.5f; wd1h[3]=t1.w*0.5f;
    }
    const float bdh = __ldg(b_d) * 0.5f;
    const float thc = tanhf_fast(bdh);

    // ---- lane geometry (invariant) ----
    const int kc = 31 * c + lane - 1;     // own patch col (may be -1 or >510)
    const int CB = kc + 1;                // own cell col
    const float hfk = ((unsigned)kc <= 510u) ? 0.5f : 0.0f;
    const int colf = (int)((unsigned)kc <= 510u) + (int)((unsigned)CB <= 510u);
    const float rcp_mid  = (colf == 2) ? 0.25f : 0.5f;   // interior cell rows
    const float rcp_edge = (colf == 2) ? 0.5f  : 1.0f;   // cell rows 0 and 511
    const bool cell_ok = (lane < 31) && (CB <= 511);

    // clamped column bases (OOB patches have hf=0; clamped garbage never escapes)
    const int gcL = 2 * kc;
    const int colO = min(max(gcL, 0), 1022);       // own block cols
    const int colR = min(max(gcL + 2, 0), 1022);   // right block cols

    const float* ibase = img + (size_t)im * IMG_PIX;
    const float* pO = ibase + colO;
    const float* pR = ibase + colR;
    float* op = out + (size_t)im * IMG_PIX + (size_t)(32 * s) * IW + 2 * CB;

    // loop-side load: row needs only upper clamp (2b >= 0 in steady loop)
    auto LOADBR = [&](int b, float4& O, float4& R) {
        const int ro = min(2 * b, 1022);
        const long long off = (long long)ro * IW;
        const float2 ot  = *(const float2*)(pO + off);
        const float2 rt  = *(const float2*)(pR + off);
        const float2 obm = *(const float2*)(pO + off + IW);
        const float2 rb  = *(const float2*)(pR + off + IW);
        O = make_float4(ot.x, ot.y, obm.x, obm.y);
        R = make_float4(rt.x, rt.y, rb.x, rb.y);
    };
    // prologue load: full clamp (row may be negative)
    auto LOADBR_C = [&](int b, float4& O, float4& R) {
        const int ro = min(max(2 * b, 0), 1022);
        const long long off = (long long)ro * IW;
        const float2 ot  = *(const float2*)(pO + off);
        const float2 rt  = *(const float2*)(pR + off);
        const float2 obm = *(const float2*)(pO + off + IW);
        const float2 rb  = *(const float2*)(pR + off + IW);
        O = make_float4(ot.x, ot.y, obm.x, obm.y);
        R = make_float4(rt.x, rt.y, rb.x, rb.y);
    };

// conv raw (ReLU deferred into argmax epilog)
#define CONVB(e, B) do { \
        cv0[e] = fmaf(wc0.x, (B).x, fmaf(wc0.y, (B).y, fmaf(wc0.z, (B).z, fmaf(wc0.w, (B).w, bc.x)))); \
        cv1[e] = fmaf(wc1.x, (B).x, fmaf(wc1.y, (B).y, fmaf(wc1.z, (B).z, fmaf(wc1.w, (B).w, bc.y)))); \
        } while (0)

    // raw conv values in cv -> argmax (deferred ReLU) -> z -> tanh sets
    // (R13 structure: hf/hfc computed per call from PR)
#define PATCH_CORE(PR)                                                        \
        int am0 = 0, am1 = 0;                                                 \
        float mv0 = cv0[0], mv1 = cv1[0];                                     \
        _Pragma("unroll")                                                     \
        for (int e = 1; e < 4; e++) {                                         \
            if (cv0[e] > mv0) { mv0 = cv0[e]; am0 = e; }                      \
            if (cv1[e] > mv1) { mv1 = cv1[e]; am1 = e; }                      \
        }                                                                     \
        am0 = (mv0 > 0.0f) ? am0 : 0;  mv0 = fmaxf(mv0, 0.0f);                \
        am1 = (mv1 > 0.0f) ? am1 : 0;  mv1 = fmaxf(mv1, 0.0f);                \
        const float z0 = fmaxf(fmaf(mv0, wb.x, fmaf(mv1, wb.y, bb.x)), 0.0f); \
        const float z1 = fmaxf(fmaf(mv0, wb.z, fmaf(mv1, wb.w, bb.y)), 0.0f); \
        const float zz1 = (am0 == am1) ? z1 : 0.0f;                           \
        const float hf = ((unsigned)(PR) <= 510u) ? hfk : 0.0f;               \
        const float hfc = fmaf(thc, hf, hf);                                  \
        float th0s[4], th1s[4];                                               \
        _Pragma("unroll")                                                     \
        for (int pq = 0; pq < 4; pq++) {                                      \
            th0s[pq] = fmaf(tanhf_fast(fmaf(z0, wd0h[pq], fmaf(zz1, wd1h[pq], bdh))), hf, hf); \
            th1s[pq] = fmaf(tanhf_fast(fmaf(z1, wd1h[pq], bdh)), hf, hf);     \
        }

#define GRP(dst, g) do {                                                      \
        const bool p0 = (am0 == (g));                                         \
        const bool p1 = (am1 == (g));                                         \
        (dst).x = p0 ? th0s[0] : (p1 ? th1s[0] : hfc);                        \
        (dst).y = p0 ? th0s[1] : (p1 ? th1s[1] : hfc);                        \
        (dst).z = p0 ? th0s[2] : (p1 ? th1s[2] : hfc);                        \
        (dst).w = p0 ? th0s[3] : (p1 ? th1s[3] : hfc); } while (0)

    // ---- window init: Ow[1]=block row pr0, Ow[0]=block row pr0+1 ----
    float4 Ow[2], Rw[2];
    const int pr0 = 16 * s - 1;           // warm-up patch row
    LOADBR_C(pr0,     Ow[1], Rw[1]);
    LOADBR_C(pr0 + 1, Ow[0], Rw[0]);

    float4 carry;
    {   // ---- peeled warm-up (i=0): only BL/BR groups needed ----
        float cv0[4], cv1[4];
        CONVB(0, Ow[1]); CONVB(1, Rw[1]); CONVB(2, Ow[0]); CONVB(3, Rw[0]);
        LOADBR(pr0 + 2, Ow[1], Rw[1]);    // refill slot lo=1 with row pr0+2
        PATCH_CORE(pr0)
        float4 gBL, gBR;
        GRP(gBL, 2);
        GRP(gBR, 3);
        carry.x = gBR.x + __shfl_down_sync(0xffffffffu, gBL.x, 1);
        carry.y = gBR.y + __shfl_down_sync(0xffffffffu, gBL.y, 1);
        carry.z = gBR.z + __shfl_down_sync(0xffffffffu, gBL.z, 1);
        carry.w = gBR.w + __shfl_down_sync(0xffffffffu, gBL.w, 1);
    }

#pragma unroll 2
    for (int i = 1; i <= SEG_ROWS; i++) {
        const int pr = pr0 + i;           // patch row (== emitted cell row)
        const int lo = (i + 1) & 1;       // slot of block row pr
        const int hi = i & 1;             // slot of block row pr+1

        float cv0[4], cv1[4];
        CONVB(0, Ow[lo]); CONVB(1, Rw[lo]); CONVB(2, Ow[hi]); CONVB(3, Rw[hi]);
        LOADBR(pr + 2, Ow[lo], Rw[lo]);   // refill consumed slot

        PATCH_CORE(pr)

        float4 gTL, gTR, gBL, gBR;
        GRP(gTL, 0); GRP(gTR, 1); GRP(gBL, 2); GRP(gBR, 3);

        // horizontal routing from lane+1
        float4 nTL, nBL;
        nTL.x = __shfl_down_sync(0xffffffffu, gTL.x, 1);
        nTL.y = __shfl_down_sync(0xffffffffu, gTL.y, 1);
        nTL.z = __shfl_down_sync(0xffffffffu, gTL.z, 1);
        nTL.w = __shfl_down_sync(0xffffffffu, gTL.w, 1);
        nBL.x = __shfl_down_sync(0xffffffffu, gBL.x, 1);
        nBL.y = __shfl_down_sync(0xffffffffu, gBL.y, 1);
        nBL.z = __shfl_down_sync(0xffffffffu, gBL.z, 1);
        nBL.w = __shfl_down_sync(0xffffffffu, gBL.w, 1);

        // emit cell row pr
        if (cell_ok) {
            const float rcp = (pr == 0 || pr == 511) ? rcp_edge : rcp_mid;
            const float pix00 = (carry.x + gTR.x) + nTL.x;
            const float pix01 = (carry.y + gTR.y) + nTL.y;
            const float pix10 = (carry.z + gTR.z) + nTL.z;
            const float pix11 = (carry.w + gTR.w) + nTL.w;
            *(float2*)(op)      = make_float2(pix00 * rcp, pix01 * rcp);
            *(float2*)(op + IW) = make_float2(pix10 * rcp, pix11 * rcp);
        }
        op += 2 * IW;

        // vertical carry for next cell row
        carry.x = gBR.x + nBL.x;
        carry.y = gBR.y + nBL.y;
        carry.z = gBR.z + nBL.z;
        carry.w = gBR.w + nBL.w;
    }
#undef GRP
#undef PATCH_CORE
#undef CONVB
}

extern "C" void kernel_launch(void* const* d_in, const int* in_sizes, int n_in,
                              void* d_out, int out_size) {
    const float* img    = (const float*)d_in[0];
    const float* w_conv = (const float*)d_in[1];
    const float* b_conv = (const float*)d_in[2];
    const float* W_b    = (const float*)d_in[3];
    const float* b_b    = (const float*)d_in[4];
    const float* W_d    = (const float*)d_in[5];
    const float* b_d    = (const float*)d_in[6];
    float* out = (float*)d_out;

    // 8 imgs x 32 segments x 17 col-warps = 4352 warps / 4 per block
    dim3 grid(8 * NSEG * COLW / WPB);   // 1088 blocks
    dim3 block(128);
    ae_kernel<<<grid, block>>>(img, w_conv, b_conv, W_b, b_b, W_d, b_d, out);
}